// round 7
// baseline (speedup 1.0000x reference)
#include <cuda_runtime.h>
#include <math_constants.h>

#define N_NODES 8192
#define F_IN    256
#define F_OUT   64
#define ALPHA   0.2f
#define NEG_BIG -9e15f
#define SAFE_M  1e10f   // ULP(m) >= 596 >> 88 -> all non-equal entries underflow to exactly 0

// Scratch (__device__ globals: allocation-free rule)
__device__ float          g_h[N_NODES * F_OUT];   // 2 MB
__device__ float          g_ssrc[N_NODES];
__device__ float          g_sdst[N_NODES];
__device__ float          g_m[N_NODES];
__device__ float          g_cand_key[N_NODES];    // sdst sorted ascending
__device__ unsigned short g_cand_idx[N_NODES];    // matching j indices
__device__ int            g_flag_list[N_NODES];
__device__ int            g_nflag;
__device__ float          g_acc2[N_NODES * 65];   // per-flagged-row: 64 dims + l

// ---------------------------------------------------------------------------
// Kernel A: h = nodes @ W (8192x256 @ 256x64), fused s_src/s_dst epilogue.
// Also resets g_nflag and zeroes g_acc2 (graph-replay safe).
// ---------------------------------------------------------------------------
__global__ __launch_bounds__(256) void gemm_h_kernel(
    const float* __restrict__ nodes, const float* __restrict__ W,
    const float* __restrict__ a)
{
    __shared__ float As[32][68];
    __shared__ float Bs[64][68];

    const int tid = threadIdx.x;
    const int rowBase = blockIdx.x * 32;
    const int tr = tid >> 4;       // 2 rows each
    const int tc = tid & 15;       // 4 cols each

    {
        int gt = blockIdx.x * 256 + tid;
        if (gt == 0) g_nflag = 0;
        for (int t = gt; t < N_NODES * 65; t += 256 * 256)
            g_acc2[t] = 0.0f;
    }

    float acc[2][4] = {};

    for (int k0 = 0; k0 < F_IN; k0 += 64) {
#pragma unroll
        for (int it = 0; it < 2; it++) {
            int idx = tid + it * 256;
            int r   = idx >> 4;
            int kq  = (idx & 15) * 4;
            float4 vv = *(const float4*)(nodes + (size_t)(rowBase + r) * F_IN + k0 + kq);
            *(float4*)(&As[r][kq]) = vv;
        }
#pragma unroll
        for (int it = 0; it < 4; it++) {
            int idx = tid + it * 256;
            int k   = idx >> 4;
            int nq  = (idx & 15) * 4;
            *(float4*)(&Bs[k][nq]) = *(const float4*)(W + (size_t)(k0 + k) * F_OUT + nq);
        }
        __syncthreads();

#pragma unroll
        for (int kk = 0; kk < 64; kk++) {
            float a0 = As[tr * 2 + 0][kk];
            float a1 = As[tr * 2 + 1][kk];
            float4 b4 = *(const float4*)(&Bs[kk][tc * 4]);
            acc[0][0] += a0 * b4.x; acc[0][1] += a0 * b4.y; acc[0][2] += a0 * b4.z; acc[0][3] += a0 * b4.w;
            acc[1][0] += a1 * b4.x; acc[1][1] += a1 * b4.y; acc[1][2] += a1 * b4.z; acc[1][3] += a1 * b4.w;
        }
        __syncthreads();
    }

#pragma unroll
    for (int rr = 0; rr < 2; rr++) {
        float4 o = make_float4(acc[rr][0], acc[rr][1], acc[rr][2], acc[rr][3]);
        *(float4*)(g_h + (size_t)(rowBase + tr * 2 + rr) * F_OUT + tc * 4) = o;
    }

    // Fused score epilogue
    float4 Asv = *(const float4*)(a + tc * 4);
    float4 Adv = *(const float4*)(a + F_OUT + tc * 4);
#pragma unroll
    for (int rr = 0; rr < 2; rr++) {
        float ps = acc[rr][0] * Asv.x + acc[rr][1] * Asv.y + acc[rr][2] * Asv.z + acc[rr][3] * Asv.w;
        float pd = acc[rr][0] * Adv.x + acc[rr][1] * Adv.y + acc[rr][2] * Adv.z + acc[rr][3] * Adv.w;
#pragma unroll
        for (int o = 1; o < 16; o <<= 1) {
            ps += __shfl_xor_sync(0xffffffffu, ps, o);
            pd += __shfl_xor_sync(0xffffffffu, pd, o);
        }
        if (tc == 0) {
            int row = rowBase + tr * 2 + rr;
            g_ssrc[row] = ps;
            g_sdst[row] = pd;
        }
    }
}

// ---------------------------------------------------------------------------
// Kernel B: bitonic index-sort of sdst (ascending), single block, 48KB smem.
// ---------------------------------------------------------------------------
__global__ __launch_bounds__(1024) void sort_kernel()
{
    __shared__ float          skey[N_NODES];   // 32 KB
    __shared__ unsigned short sidx[N_NODES];   // 16 KB  (total exactly 48 KB)

    const int tid = threadIdx.x;
    for (int i = tid; i < N_NODES; i += 1024) {
        skey[i] = g_sdst[i];
        sidx[i] = (unsigned short)i;
    }
    __syncthreads();

    for (int k = 2; k <= N_NODES; k <<= 1) {
        for (int j = k >> 1; j > 0; j >>= 1) {
#pragma unroll 4
            for (int t = tid; t < N_NODES; t += 1024) {
                int ixj = t ^ j;
                if (ixj > t) {
                    bool up = ((t & k) == 0);
                    float a = skey[t], b = skey[ixj];
                    bool sw = up ? (a > b) : (a < b);
                    if (sw) {
                        skey[t] = b; skey[ixj] = a;
                        unsigned short ti = sidx[t];
                        sidx[t] = sidx[ixj]; sidx[ixj] = ti;
                    }
                }
            }
            __syncthreads();
        }
    }

    for (int i = tid; i < N_NODES; i += 1024) {
        g_cand_key[i] = skey[i];
        g_cand_idx[i] = sidx[i];
    }
}

// ---------------------------------------------------------------------------
// Kernel C: winner pick. Warp per row. For masked j (adj<=0.5),
// v = leaky(ssrc+sdst_j)*NEG_BIG is monotone non-increasing along ascending
// sdst, so the row max over masked j is the FIRST masked candidate in sorted
// order, and its float-equal tie run is contiguous. Probe adj only at sorted
// candidates (expected ~2 probes/row). If winner |v| < SAFE_M (or no masked
// entry), flag for the exact dense pass.
// ---------------------------------------------------------------------------
__global__ __launch_bounds__(256) void pick_kernel(
    const float* __restrict__ adj, float* __restrict__ out)
{
    const int warp = threadIdx.x >> 5;
    const int lane = threadIdx.x & 31;
    const int row  = blockIdx.x * 8 + warp;

    const float ssrc = g_ssrc[row];
    const float* adjrow = adj + (size_t)row * N_NODES;

    float m = 0.0f;
    bool found = false, flagged = false;
    float hacc0 = 0.0f, hacc1 = 0.0f, cnt = 0.0f;
    int base = 0;

    while (true) {
        const int k = base + lane;                  // base <= 8160 -> k < 8192
        float key = g_cand_key[k];
        int   idx = (int)g_cand_idx[k];
        // EXACT same fp32 expression as the dense path:
        float s  = ssrc + key;
        float e  = fmaxf(s, ALPHA * s);
        float vm = e * NEG_BIG;
        float av = __ldg(adjrow + idx);
        bool masked = !(av > 0.5f);

        unsigned mball = __ballot_sync(0xffffffffu, masked);
        if (!found) {
            if (mball == 0) {
                base += 32;
                if (base >= N_NODES) { flagged = true; break; }
                continue;
            }
            int b0 = __ffs(mball) - 1;
            m = __shfl_sync(0xffffffffu, vm, b0);
            found = true;
        }
        unsigned tie = __ballot_sync(0xffffffffu, masked && (vm == m));
        while (tie) {
            int b = __ffs(tie) - 1;
            tie &= tie - 1;
            int j = __shfl_sync(0xffffffffu, idx, b);
            float2 hv = *(const float2*)(g_h + (size_t)j * F_OUT + lane * 2);
            hacc0 += hv.x;
            hacc1 += hv.y;
            cnt   += 1.0f;
        }
        float vend = __shfl_sync(0xffffffffu, vm, 31);   // smallest vm in window
        base += 32;
        if (vend != m || base >= N_NODES) break;          // run cannot extend
    }

    if (!flagged && m >= SAFE_M) {
        float inv = 1.0f / cnt;
        float o0 = hacc0 * inv;
        float o1 = hacc1 * inv;
        o0 = fmaxf(o0, ALPHA * o0);
        o1 = fmaxf(o1, ALPHA * o1);
        *(float2*)(out + (size_t)row * F_OUT + lane * 2) = make_float2(o0, o1);
    } else if (lane == 0) {
        int p = atomicAdd(&g_nflag, 1);
        g_flag_list[p] = row;
    }
}

// ---------------------------------------------------------------------------
// Kernel D (pass2m): true row max for flagged rows (dense scan).
// ---------------------------------------------------------------------------
__global__ __launch_bounds__(256) void pass2m_kernel(const float* __restrict__ adj)
{
    __shared__ float red[8];
    const int nflag = g_nflag;
    const int tid  = threadIdx.x;
    const int warp = tid >> 5;
    const int lane = tid & 31;

    for (int f = blockIdx.x; f < nflag; f += gridDim.x) {
        const int row = g_flag_list[f];
        const float ssrc = g_ssrc[row];
        const float* adjrow = adj + (size_t)row * N_NODES;

        float mx = -CUDART_INF_F;
        for (int j = tid; j < N_NODES; j += 256) {
            float av = __ldg(adjrow + j);
            float s  = ssrc + g_sdst[j];
            float e  = fmaxf(s, ALPHA * s);
            float v  = (av > 0.5f) ? e : e * NEG_BIG;
            mx = fmaxf(mx, v);
        }
#pragma unroll
        for (int o = 16; o; o >>= 1)
            mx = fmaxf(mx, __shfl_xor_sync(0xffffffffu, mx, o));
        if (lane == 0) red[warp] = mx;
        __syncthreads();
        if (tid == 0) {
            float r = red[0];
#pragma unroll
            for (int w = 1; w < 8; w++) r = fmaxf(r, red[w]);
            g_m[row] = r;
        }
        __syncthreads();
    }
}

// ---------------------------------------------------------------------------
// Kernel E (pass2a): dense softmax partials for flagged rows, spread wide.
// ---------------------------------------------------------------------------
__global__ __launch_bounds__(256) void pass2a_kernel(const float* __restrict__ adj)
{
    const int nflag = g_nflag;
    if (nflag == 0) return;
    const int tid = threadIdx.x;
    const int d   = tid & 63;
    const int jl  = tid >> 6;          // 0..3
    const int total = nflag * 64;

    for (int w = blockIdx.x; w < total; w += gridDim.x) {
        const int f    = w >> 6;
        const int row  = g_flag_list[f];
        const float m  = g_m[row];
        const float ssrc = g_ssrc[row];
        const int j0   = (w & 63) * 128;
        const float* adjrow = adj + (size_t)row * N_NODES + j0;

        float acc = 0.0f;
        float lsum = 0.0f;
#pragma unroll 8
        for (int t = 0; t < 32; t++) {
            int j = jl + t * 4;
            float av = __ldg(adjrow + j);
            float s = ssrc + g_sdst[j0 + j];
            float e = fmaxf(s, ALPHA * s);
            float v = (av > 0.5f) ? e : e * NEG_BIG;
            float p = __expf(v - m);
            acc += p * g_h[(size_t)(j0 + j) * F_OUT + d];
            if (d == 0) lsum += p;
        }
        atomicAdd(&g_acc2[f * 65 + d], acc);
        if (d == 0) atomicAdd(&g_acc2[f * 65 + 64], lsum);
    }
}

// ---------------------------------------------------------------------------
// Kernel F (pass2b): normalize flagged rows.
// ---------------------------------------------------------------------------
__global__ __launch_bounds__(64) void pass2b_kernel(float* __restrict__ out)
{
    const int nflag = g_nflag;
    const int d = threadIdx.x;
    for (int f = blockIdx.x; f < nflag; f += gridDim.x) {
        const int row = g_flag_list[f];
        float l = g_acc2[f * 65 + 64];
        float o = g_acc2[f * 65 + d] / l;
        o = fmaxf(o, ALPHA * o);
        out[(size_t)row * F_OUT + d] = o;
    }
}

// ---------------------------------------------------------------------------
extern "C" void kernel_launch(void* const* d_in, const int* in_sizes, int n_in,
                              void* d_out, int out_size)
{
    const float* nodes = (const float*)d_in[0];   // [8192, 256]
    const float* adj   = (const float*)d_in[1];   // [8192, 8192]
    const float* W     = (const float*)d_in[2];   // [256, 64]
    const float* a     = (const float*)d_in[3];   // [128]
    float* out = (float*)d_out;                   // [8192, 64]

    gemm_h_kernel<<<N_NODES / 32, 256>>>(nodes, W, a);
    sort_kernel<<<1, 1024>>>();
    pick_kernel<<<N_NODES / 8, 256>>>(adj, out);
    pass2m_kernel<<<64, 256>>>(adj);
    pass2a_kernel<<<2048, 256>>>(adj);
    pass2b_kernel<<<64, 64>>>(out);
}

// round 11
// speedup vs baseline: 1.3920x; 1.3920x over previous
#include <cuda_runtime.h>
#include <math_constants.h>

#define N_NODES 8192
#define F_IN    256
#define F_OUT   64
#define ALPHA   0.2f
#define NEG_BIG -9e15f
#define SAFE_M  1e10f   // ULP(m) >> 88 -> all non-equal entries underflow to exactly 0
#define C_CAND  256

// Scratch (__device__ globals: allocation-free rule)
__device__ float          g_h[N_NODES * F_OUT];   // 2 MB
__device__ float          g_ssrc[N_NODES];
__device__ float          g_sdst[N_NODES];
__device__ float          g_run_key[N_NODES];     // 8 sorted runs of 1024
__device__ unsigned short g_run_idx[N_NODES];
__device__ float          g_cand_key[C_CAND];     // global bottom-256 of sdst, ascending
__device__ unsigned short g_cand_idx[C_CAND];
__device__ unsigned int   g_m_u[N_NODES];         // encoded row max per flag slot
__device__ int            g_flag_list[N_NODES];
__device__ int            g_nflag;
__device__ float          g_acc2[N_NODES * 65];   // per-flagged-row: 64 dims + l

// Monotone float<->uint encoding for atomicMax
__device__ __forceinline__ unsigned int enc_f(float f) {
    unsigned int u = __float_as_uint(f);
    return (u & 0x80000000u) ? ~u : (u | 0x80000000u);
}
__device__ __forceinline__ float dec_f(unsigned int u) {
    return (u & 0x80000000u) ? __uint_as_float(u & 0x7FFFFFFFu) : __uint_as_float(~u);
}

// ---------------------------------------------------------------------------
// Kernel A: h = nodes @ W (8192x256 @ 256x64), fused s_src/s_dst epilogue.
// 16-row tiles -> 512 blocks. Also resets flag state (graph-replay safe).
// ---------------------------------------------------------------------------
__global__ __launch_bounds__(256) void gemm_h_kernel(
    const float* __restrict__ nodes, const float* __restrict__ W,
    const float* __restrict__ a)
{
    __shared__ float As[16][68];
    __shared__ float Bs[64][68];

    const int tid = threadIdx.x;
    const int rowBase = blockIdx.x * 16;
    const int tr = tid >> 4;       // 0..15 -> 1 row each
    const int tc = tid & 15;       // 4 cols each

    // Housekeeping for later kernels
    {
        int gt = blockIdx.x * 256 + tid;
        if (gt == 0) g_nflag = 0;
        for (int t = gt; t < N_NODES * 65; t += 512 * 256)
            g_acc2[t] = 0.0f;
        if (gt < N_NODES) g_m_u[gt] = 0u;   // dec(0) < any real value
    }

    float acc[4] = {};

    for (int k0 = 0; k0 < F_IN; k0 += 64) {
        // A tile: 16x64 = 256 float4 -> 1 per thread
        {
            int r  = tid >> 4;
            int kq = (tid & 15) * 4;
            *(float4*)(&As[r][kq]) =
                *(const float4*)(nodes + (size_t)(rowBase + r) * F_IN + k0 + kq);
        }
        // B tile: 64x64 = 1024 float4 -> 4 per thread
#pragma unroll
        for (int it = 0; it < 4; it++) {
            int idx = tid + it * 256;
            int k   = idx >> 4;
            int nq  = (idx & 15) * 4;
            *(float4*)(&Bs[k][nq]) = *(const float4*)(W + (size_t)(k0 + k) * F_OUT + nq);
        }
        __syncthreads();

#pragma unroll
        for (int kk = 0; kk < 64; kk++) {
            float a0 = As[tr][kk];
            float4 b4 = *(const float4*)(&Bs[kk][tc * 4]);
            acc[0] += a0 * b4.x; acc[1] += a0 * b4.y;
            acc[2] += a0 * b4.z; acc[3] += a0 * b4.w;
        }
        __syncthreads();
    }

    *(float4*)(g_h + (size_t)(rowBase + tr) * F_OUT + tc * 4) =
        make_float4(acc[0], acc[1], acc[2], acc[3]);

    // Fused score epilogue: ssrc = h . a[:64], sdst = h . a[64:]
    float4 Asv = *(const float4*)(a + tc * 4);
    float4 Adv = *(const float4*)(a + F_OUT + tc * 4);
    float ps = acc[0] * Asv.x + acc[1] * Asv.y + acc[2] * Asv.z + acc[3] * Asv.w;
    float pd = acc[0] * Adv.x + acc[1] * Adv.y + acc[2] * Adv.z + acc[3] * Adv.w;
#pragma unroll
    for (int o = 1; o < 16; o <<= 1) {
        ps += __shfl_xor_sync(0xffffffffu, ps, o);
        pd += __shfl_xor_sync(0xffffffffu, pd, o);
    }
    if (tc == 0) {
        g_ssrc[rowBase + tr] = ps;
        g_sdst[rowBase + tr] = pd;
    }
}

// ---------------------------------------------------------------------------
// Kernel B1: 8 parallel blocks each bitonic-sort a 1024-run of sdst ascending.
// ---------------------------------------------------------------------------
__global__ __launch_bounds__(1024) void sort1_kernel()
{
    __shared__ float          skey[1024];
    __shared__ unsigned short sidx[1024];

    const int tid  = threadIdx.x;
    const int base = blockIdx.x * 1024;
    skey[tid] = g_sdst[base + tid];
    sidx[tid] = (unsigned short)(base + tid);
    __syncthreads();

    for (int k = 2; k <= 1024; k <<= 1) {
        for (int j = k >> 1; j > 0; j >>= 1) {
            int ixj = tid ^ j;
            if (ixj > tid) {
                bool up = ((tid & k) == 0);
                float a = skey[tid], b = skey[ixj];
                if (up ? (a > b) : (a < b)) {
                    skey[tid] = b; skey[ixj] = a;
                    unsigned short t = sidx[tid]; sidx[tid] = sidx[ixj]; sidx[ixj] = t;
                }
            }
            __syncthreads();
        }
    }
    g_run_key[base + tid] = skey[tid];
    g_run_idx[base + tid] = sidx[tid];
}

// ---------------------------------------------------------------------------
// Kernel B2: merge heads. Bottom-256 global is contained in the union of the
// first 256 of each sorted run (within-run rank <= global rank). Sort the
// 8x256=2048 union, emit first 256.
// ---------------------------------------------------------------------------
__global__ __launch_bounds__(1024) void sort2_kernel()
{
    __shared__ float          skey[2048];
    __shared__ unsigned short sidx[2048];

    const int tid = threadIdx.x;
    for (int t = tid; t < 2048; t += 1024) {
        int run = t >> 8;            // 0..7
        int off = t & 255;
        skey[t] = g_run_key[run * 1024 + off];
        sidx[t] = g_run_idx[run * 1024 + off];
    }
    __syncthreads();

    for (int k = 2; k <= 2048; k <<= 1) {
        for (int j = k >> 1; j > 0; j >>= 1) {
            for (int t = tid; t < 2048; t += 1024) {
                int ixj = t ^ j;
                if (ixj > t) {
                    bool up = ((t & k) == 0);
                    float a = skey[t], b = skey[ixj];
                    if (up ? (a > b) : (a < b)) {
                        skey[t] = b; skey[ixj] = a;
                        unsigned short tt = sidx[t]; sidx[t] = sidx[ixj]; sidx[ixj] = tt;
                    }
                }
            }
            __syncthreads();
        }
    }
    if (tid < C_CAND) {
        g_cand_key[tid] = skey[tid];
        g_cand_idx[tid] = sidx[tid];
    }
}

// ---------------------------------------------------------------------------
// Kernel C: winner pick. Warp per row. For masked j (adj<=0.5),
// v = leaky(ssrc+sdst_j)*NEG_BIG is monotone non-increasing along ascending
// sdst, so the row max over masked j is the FIRST masked candidate, and its
// float-equal tie run is contiguous. Probe adj only at candidates (expected
// ~2 probes/row). Flag for exact dense fallback if: no masked candidate in
// the 256-window, tie run reaches the window end, or winner |v| < SAFE_M.
// ---------------------------------------------------------------------------
__global__ __launch_bounds__(256) void pick_kernel(
    const float* __restrict__ adj, float* __restrict__ out)
{
    __shared__ float          ck[C_CAND];
    __shared__ unsigned short ci[C_CAND];
    ck[threadIdx.x] = g_cand_key[threadIdx.x];
    ci[threadIdx.x] = g_cand_idx[threadIdx.x];
    __syncthreads();

    const int warp = threadIdx.x >> 5;
    const int lane = threadIdx.x & 31;
    const int row  = blockIdx.x * 8 + warp;

    const float ssrc = g_ssrc[row];
    const float* adjrow = adj + (size_t)row * N_NODES;

    float m = 0.0f;
    bool found = false, open_end = false;
    float hacc0 = 0.0f, hacc1 = 0.0f, cnt = 0.0f;
    int base = 0;

    while (base < C_CAND) {
        const int k = base + lane;
        float key = ck[k];
        int   idx = (int)ci[k];
        // EXACT same fp32 expression as the dense path:
        float s  = ssrc + key;
        float e  = fmaxf(s, ALPHA * s);
        float vm = e * NEG_BIG;
        float av = __ldg(adjrow + idx);
        bool masked = !(av > 0.5f);

        unsigned mball = __ballot_sync(0xffffffffu, masked);
        if (!found) {
            if (mball == 0) { base += 32; continue; }
            int b0 = __ffs(mball) - 1;
            m = __shfl_sync(0xffffffffu, vm, b0);
            found = true;
        }
        unsigned tie = __ballot_sync(0xffffffffu, masked && (vm == m));
        while (tie) {
            int b = __ffs(tie) - 1;
            tie &= tie - 1;
            int j = __shfl_sync(0xffffffffu, idx, b);
            float2 hv = *(const float2*)(g_h + (size_t)j * F_OUT + lane * 2);
            hacc0 += hv.x;
            hacc1 += hv.y;
            cnt   += 1.0f;
        }
        float vend = __shfl_sync(0xffffffffu, vm, 31);   // smallest vm in window
        base += 32;
        if (vend != m) { open_end = false; break; }      // tie run closed
        open_end = true;                                 // may extend past window
    }

    bool flagged = (!found) || open_end;

    if (!flagged && m >= SAFE_M) {
        float inv = 1.0f / cnt;
        float o0 = hacc0 * inv;
        float o1 = hacc1 * inv;
        o0 = fmaxf(o0, ALPHA * o0);
        o1 = fmaxf(o1, ALPHA * o1);
        *(float2*)(out + (size_t)row * F_OUT + lane * 2) = make_float2(o0, o1);
    } else if (lane == 0) {
        int p = atomicAdd(&g_nflag, 1);
        g_flag_list[p] = row;
    }
}

// ---------------------------------------------------------------------------
// Kernel D (pass2m): true row max for flagged rows, spread wide.
// nflag*32 chunks of 256 elements; warp-reduce + encoded atomicMax.
// ---------------------------------------------------------------------------
__global__ __launch_bounds__(256) void pass2m_kernel(const float* __restrict__ adj)
{
    const int nflag = g_nflag;
    if (nflag == 0) return;
    const int tid  = threadIdx.x;
    const int lane = tid & 31;
    const int total = nflag * 32;

    for (int w = blockIdx.x; w < total; w += gridDim.x) {
        const int f   = w >> 5;
        const int row = g_flag_list[f];
        const int j0  = (w & 31) * 256;
        const float ssrc = g_ssrc[row];

        int j = j0 + tid;
        float av = __ldg(adj + (size_t)row * N_NODES + j);
        float s  = ssrc + g_sdst[j];
        float e  = fmaxf(s, ALPHA * s);
        float v  = (av > 0.5f) ? e : e * NEG_BIG;
#pragma unroll
        for (int o = 16; o; o >>= 1)
            v = fmaxf(v, __shfl_xor_sync(0xffffffffu, v, o));
        if (lane == 0) atomicMax(&g_m_u[f], enc_f(v));
    }
}

// ---------------------------------------------------------------------------
// Kernel E (pass2a): dense softmax partials for flagged rows, spread wide.
// ---------------------------------------------------------------------------
__global__ __launch_bounds__(256) void pass2a_kernel(const float* __restrict__ adj)
{
    const int nflag = g_nflag;
    if (nflag == 0) return;
    const int tid = threadIdx.x;
    const int d   = tid & 63;
    const int jl  = tid >> 6;          // 0..3
    const int total = nflag * 64;

    for (int w = blockIdx.x; w < total; w += gridDim.x) {
        const int f    = w >> 6;
        const int row  = g_flag_list[f];
        const float m  = dec_f(g_m_u[f]);
        const float ssrc = g_ssrc[row];
        const int j0   = (w & 63) * 128;
        const float* adjrow = adj + (size_t)row * N_NODES + j0;

        float acc = 0.0f;
        float lsum = 0.0f;
#pragma unroll 8
        for (int t = 0; t < 32; t++) {
            int j = jl + t * 4;
            float av = __ldg(adjrow + j);
            float s = ssrc + g_sdst[j0 + j];
            float e = fmaxf(s, ALPHA * s);
            float v = (av > 0.5f) ? e : e * NEG_BIG;
            float p = __expf(v - m);
            acc += p * g_h[(size_t)(j0 + j) * F_OUT + d];
            if (d == 0) lsum += p;
        }
        atomicAdd(&g_acc2[f * 65 + d], acc);
        if (d == 0) atomicAdd(&g_acc2[f * 65 + 64], lsum);
    }
}

// ---------------------------------------------------------------------------
// Kernel F (pass2b): normalize flagged rows.
// ---------------------------------------------------------------------------
__global__ __launch_bounds__(64) void pass2b_kernel(float* __restrict__ out)
{
    const int nflag = g_nflag;
    const int d = threadIdx.x;
    for (int f = blockIdx.x; f < nflag; f += gridDim.x) {
        const int row = g_flag_list[f];
        float l = g_acc2[f * 65 + 64];
        float o = g_acc2[f * 65 + d] / l;
        o = fmaxf(o, ALPHA * o);
        out[(size_t)row * F_OUT + d] = o;
    }
}

// ---------------------------------------------------------------------------
extern "C" void kernel_launch(void* const* d_in, const int* in_sizes, int n_in,
                              void* d_out, int out_size)
{
    const float* nodes = (const float*)d_in[0];   // [8192, 256]
    const float* adj   = (const float*)d_in[1];   // [8192, 8192]
    const float* W     = (const float*)d_in[2];   // [256, 64]
    const float* a     = (const float*)d_in[3];   // [128]
    float* out = (float*)d_out;                   // [8192, 64]

    gemm_h_kernel<<<N_NODES / 16, 256>>>(nodes, W, a);
    sort1_kernel<<<8, 1024>>>();
    sort2_kernel<<<1, 1024>>>();
    pick_kernel<<<N_NODES / 8, 256>>>(adj, out);
    pass2m_kernel<<<1024, 256>>>(adj);
    pass2a_kernel<<<2048, 256>>>(adj);
    pass2b_kernel<<<64, 64>>>(out);
}